// round 8
// baseline (speedup 1.0000x reference)
#include <cuda_runtime.h>
#include <cuda_bf16.h>
#include <math.h>
#include <stdint.h>

#define VOCAB 50257
#define DMEAN 1024
#define DMV   1024
#define BATCH 32
#define SEQL  128

// ---- k2 tf32 pipeline config (256 threads / 8 warps per block) ----
#define TM      128                       // vocab rows per block
#define KSTG    32                        // k per stage
#define NSTG    (DMV / KSTG)              // 32 stages
#define DEPTH   4
#define AST     136                       // A k-row stride in words (conflict-free)
#define BST     40                        // B n-row stride in words
#define AW_STG  (KSTG * AST)              // 4352 words per A stage
#define BW_STG  (BATCH * BST)             // 1280 words per B stage
#define K2_SMEM ((DEPTH * AW_STG + DEPTH * BW_STG) * 4)   // 90112 B

// split k2 into two launches so ncu's -s 5 -c 1 window lands on a GEMM
#define NB2A    197                       // covers vocab [0, 25216)
#define VB_B    (NB2A * TM)               // 25216
#define NB2B    ((VOCAB - VB_B + TM - 1) / TM)   // 196

// Scratch (device globals — no runtime allocation allowed)
__device__ float g_h[BATCH * DMV];            // h fp32, [b][k]
__device__ float g_logits[BATCH * VOCAB];
__device__ float g_partial[BATCH];

// ---------------------------------------------------------------------------
// PTX helpers
// ---------------------------------------------------------------------------
#define MMA1688(c, a, bb0, bb1)                                                \
    asm volatile("mma.sync.aligned.m16n8k8.row.col.f32.tf32.tf32.f32 "         \
                 "{%0,%1,%2,%3}, {%4,%5,%6,%7}, {%8,%9}, {%0,%1,%2,%3};"       \
                 : "+f"(c[0]), "+f"(c[1]), "+f"(c[2]), "+f"(c[3])              \
                 : "r"(a[0]), "r"(a[1]), "r"(a[2]), "r"(a[3]),                 \
                   "r"(bb0), "r"(bb1))

__device__ __forceinline__ void cp_async16(uint32_t dst, const void* src) {
    asm volatile("cp.async.cg.shared.global [%0], [%1], 16;"
                 :: "r"(dst), "l"(src) : "memory");
}
__device__ __forceinline__ void cp_async4(uint32_t dst, const void* src) {
    asm volatile("cp.async.ca.shared.global [%0], [%1], 4;"
                 :: "r"(dst), "l"(src) : "memory");
}
__device__ __forceinline__ uint32_t lds32(uint32_t a) {
    uint32_t v;
    asm volatile("ld.shared.b32 %0, [%1];" : "=r"(v) : "r"(a));
    return v;
}
#define CP_COMMIT() asm volatile("cp.async.commit_group;" ::: "memory")
#define CP_WAIT2()  asm volatile("cp.async.wait_group 2;" ::: "memory")

// ---------------------------------------------------------------------------
// Kernel 1: h = gelu(z @ W0 + b0) -> g_h fp32 [b][k].
// Proven FFMA version (R2/R3): 128 blocks, unroll 32, coalesced W0 stream.
// ---------------------------------------------------------------------------
__global__ void __launch_bounds__(256) k1_gemm0(const float* __restrict__ z,
                                                const float* __restrict__ W0,
                                                const float* __restrict__ b0) {
    __shared__ float zs[4][DMEAN];
    const int tid = threadIdx.x;
    const int col = blockIdx.x * 64 + (tid & 63);
    const int bg  = blockIdx.y;
    const int brow = bg * 4 + (tid >> 6);

    for (int i = tid; i < 4 * DMEAN; i += 256) {
        int bb = i >> 10, kk = i & 1023;
        zs[bb][kk] = z[(bg * 4 + bb) * DMEAN + kk];
    }
    __syncthreads();

    const float* zr = zs[tid >> 6];
    const float* wp = W0 + col;
    float acc = 0.f;
#pragma unroll 32
    for (int k = 0; k < DMEAN; k++) {
        acc = fmaf(zr[k], wp[(size_t)k * DMV], acc);
    }
    float x = acc + b0[col];
    g_h[brow * DMV + col] = 0.5f * x * (1.f + erff(x * 0.70710678118654752f));
}

// ---------------------------------------------------------------------------
// Kernel 2: logits tile = h @ W1 + b1.  TF32 mma, 256 thr (8 warps: 2x R7
// warps/SMSP), DEPTH-4 cp.async pipeline. Warp w owns m rows [w*16, w*16+16).
// A tile: 4B cp.async (W1 rows only 4B-aligned; VOCAB odd).
// B tile: 16B cp.async from g_h.
// ---------------------------------------------------------------------------
__global__ void __launch_bounds__(256) k2_mma(const float* __restrict__ W1,
                                              const float* __restrict__ b1,
                                              int vb0) {
    extern __shared__ char sm[];
    const uint32_t smb = (uint32_t)__cvta_generic_to_shared(sm);
    const uint32_t bsb = smb + DEPTH * AW_STG * 4;
    const int t = threadIdx.x, w = t >> 5, lane = t & 31;
    const int vb = vb0 + blockIdx.x * TM;

    // stage fill: A = 4096 words (16x 4B/thread), B = 256 granules (1/thread)
    auto fill = [&](int s) {
        const int buf = s & (DEPTH - 1);
        const uint32_t Ab = smb + buf * AW_STG * 4;
        const uint32_t Bb = bsb + buf * BW_STG * 4;
        const int kr = s * KSTG;
#pragma unroll
        for (int i = 0; i < 16; i++) {
            int idx = t + i * 256;
            int k = idx >> 7, m = idx & 127;
            int vg = min(vb + m, VOCAB - 1);   // tail clamp (duplicates harmless)
            cp_async4(Ab + (uint32_t)(k * AST + m) * 4,
                      W1 + (size_t)(kr + k) * VOCAB + vg);
        }
        {
            int n = t >> 3, g = t & 7;
            cp_async16(Bb + (uint32_t)(n * BST + 4 * g) * 4,
                       g_h + (size_t)n * DMV + kr + 4 * g);
        }
    };

    fill(0); CP_COMMIT();
    fill(1); CP_COMMIT();
    fill(2); CP_COMMIT();

    float acc[4][4];
#pragma unroll
    for (int j = 0; j < 4; j++)
#pragma unroll
        for (int q = 0; q < 4; q++) acc[j][q] = 0.f;

    for (int s = 0; s < NSTG; s++) {
        CP_WAIT2();
        __syncthreads();                 // stage s visible; buf s-1 reusable
        if (s + 3 < NSTG) fill(s + 3);
        CP_COMMIT();                     // commit every iter (group accounting)

        const int buf = s & (DEPTH - 1);
        const uint32_t Ab = smb + buf * AW_STG * 4;
        const uint32_t Bb = bsb + buf * BW_STG * 4;
#pragma unroll
        for (int ks = 0; ks < 4; ks++) {
            const int kb = ks * 8;
            uint32_t a[4], bf[4][2];
            {
                int m = w * 16 + (lane >> 2);
                uint32_t r0 = Ab + (uint32_t)((kb + (lane & 3)) * AST + m) * 4;
                a[0] = lds32(r0);
                a[1] = lds32(r0 + 8 * 4);
                a[2] = lds32(r0 + 4 * AST * 4);
                a[3] = lds32(r0 + (4 * AST + 8) * 4);
            }
#pragma unroll
            for (int ns = 0; ns < 4; ns++) {
                int n = ns * 8 + (lane >> 2);
                uint32_t r0 = Bb + (uint32_t)(n * BST + kb + (lane & 3)) * 4;
                bf[ns][0] = lds32(r0);
                bf[ns][1] = lds32(r0 + 4 * 4);
            }
#pragma unroll
            for (int ns = 0; ns < 4; ns++)
                MMA1688(acc[ns], a, bf[ns][0], bf[ns][1]);
        }
    }

    // epilogue: + bias, store g_logits[b][v] (guard vocab tail)
    {
        int v0 = vb + w * 16 + (lane >> 2);
        int v1 = v0 + 8;
        float bi0 = b1[min(v0, VOCAB - 1)];
        float bi1 = b1[min(v1, VOCAB - 1)];
#pragma unroll
        for (int ns = 0; ns < 4; ns++) {
            int b = ns * 8 + (lane & 3) * 2;
            if (v0 < VOCAB) {
                g_logits[(size_t)b * VOCAB + v0]       = acc[ns][0] + bi0;
                g_logits[(size_t)(b + 1) * VOCAB + v0] = acc[ns][1] + bi0;
            }
            if (v1 < VOCAB) {
                g_logits[(size_t)b * VOCAB + v1]       = acc[ns][2] + bi1;
                g_logits[(size_t)(b + 1) * VOCAB + v1] = acc[ns][3] + bi1;
            }
        }
    }
}

// ---------------------------------------------------------------------------
// Kernel 3: per-row logsumexp + label gather.
// ---------------------------------------------------------------------------
__global__ void __launch_bounds__(512) k3_lse(const int* __restrict__ labels) {
    const int b = blockIdx.x;
    const int tid = threadIdx.x;
    const float* row = g_logits + (size_t)b * VOCAB;
    __shared__ float red[512];

    float m = -INFINITY;
    for (int v = tid; v < VOCAB; v += 512) m = fmaxf(m, row[v]);
    red[tid] = m; __syncthreads();
    for (int s = 256; s > 0; s >>= 1) {
        if (tid < s) red[tid] = fmaxf(red[tid], red[tid + s]);
        __syncthreads();
    }
    const float M = red[0]; __syncthreads();

    float ssum = 0.f;
    for (int v = tid; v < VOCAB; v += 512) ssum += expf(row[v] - M);
    red[tid] = ssum; __syncthreads();
    for (int s = 256; s > 0; s >>= 1) {
        if (tid < s) red[tid] += red[tid + s];
        __syncthreads();
    }
    const float Ssum = red[0]; __syncthreads();

    float g = 0.f;
    if (tid < SEQL) {
        int lv = labels[b * SEQL + tid];
        lv = max(0, min(lv, VOCAB - 1));
        g = row[lv];
    }
    red[tid] = g; __syncthreads();
    for (int s = 256; s > 0; s >>= 1) {
        if (tid < s) red[tid] += red[tid + s];
        __syncthreads();
    }
    if (tid == 0) g_partial[b] = (float)SEQL * (M + logf(Ssum)) - red[0];
}

// ---------------------------------------------------------------------------
// Kernel 4: final mean.
// ---------------------------------------------------------------------------
__global__ void k4_final(float* __restrict__ out) {
    if (threadIdx.x == 0) {
        float s = 0.f;
        for (int i = 0; i < BATCH; i++) s += g_partial[i];
        out[0] = s / (float)(BATCH * SEQL);
    }
}

// ---------------------------------------------------------------------------
extern "C" void kernel_launch(void* const* d_in, const int* in_sizes, int n_in,
                              void* d_out, int out_size) {
    const float* z      = (const float*)d_in[0];
    const int*   labels = (const int*)d_in[1];
    const float* W0     = (const float*)d_in[2];
    const float* b0     = (const float*)d_in[3];
    const float* W1     = (const float*)d_in[4];
    const float* b1     = (const float*)d_in[5];
    float* out = (float*)d_out;

    cudaFuncSetAttribute(k2_mma, cudaFuncAttributeMaxDynamicSharedMemorySize,
                         K2_SMEM);

    k1_gemm0<<<dim3(16, 8), 256>>>(z, W0, b0);         // 128 blocks (proven FFMA)
    k2_mma<<<NB2A, 256, K2_SMEM>>>(W1, b1, 0);         // vocab [0, 25216)
    k2_mma<<<NB2B, 256, K2_SMEM>>>(W1, b1, VB_B);      // vocab [25216, 50257)
    k3_lse<<<BATCH, 512>>>(labels);
    k4_final<<<1, 32>>>(out);
}

// round 10
// speedup vs baseline: 1.1779x; 1.1779x over previous
#include <cuda_runtime.h>
#include <cuda_bf16.h>
#include <math.h>
#include <stdint.h>

#define VOCAB 50257
#define DMEAN 1024
#define DMV   1024
#define BATCH 32
#define SEQL  128
#define TOTW  ((size_t)DMV * VOCAB)       // W1 total words

// ---- k2 tf32 pipeline config (256 threads / 8 warps per block) ----
#define TM      128
#define KSTG    32
#define NSTG    (DMV / KSTG)              // 32
#define DEPTH   4
#define AST     136                       // 34 x 16B granules per k-row (pad included)
#define BST     40
#define AW_STG  (KSTG * AST)              // 4352 words
#define BW_STG  (BATCH * BST)             // 1280 words
#define K2_SMEM ((DEPTH * AW_STG + DEPTH * BW_STG) * 4)   // 90112 B

#define NB2A    197                       // vocab [0, 25216)
#define VB_B    (NB2A * TM)
#define NB2B    ((VOCAB - VB_B + TM - 1) / TM)   // 196

// ---- k3 split ----
#define NSL     8
#define SLW     6283                      // ceil(VOCAB/8)

// Scratch (device globals — no runtime allocation allowed)
__device__ float g_h[BATCH * DMV];
__device__ float g_logits[BATCH * VOCAB];
__device__ float g_red[BATCH][NSL][2];    // per-slice {max, sumexp}

// ---------------------------------------------------------------------------
#define MMA1688(c, a, bb0, bb1)                                                \
    asm volatile("mma.sync.aligned.m16n8k8.row.col.f32.tf32.tf32.f32 "         \
                 "{%0,%1,%2,%3}, {%4,%5,%6,%7}, {%8,%9}, {%0,%1,%2,%3};"       \
                 : "+f"(c[0]), "+f"(c[1]), "+f"(c[2]), "+f"(c[3])              \
                 : "r"(a[0]), "r"(a[1]), "r"(a[2]), "r"(a[3]),                 \
                   "r"(bb0), "r"(bb1))

__device__ __forceinline__ void cp_async16(uint32_t dst, const void* src) {
    asm volatile("cp.async.cg.shared.global [%0], [%1], 16;"
                 :: "r"(dst), "l"(src) : "memory");
}
__device__ __forceinline__ uint32_t lds32(uint32_t a) {
    uint32_t v;
    asm volatile("ld.shared.b32 %0, [%1];" : "=r"(v) : "r"(a));
    return v;
}
#define CP_COMMIT() asm volatile("cp.async.commit_group;" ::: "memory")
#define CP_WAIT2()  asm volatile("cp.async.wait_group 2;" ::: "memory")

// ---------------------------------------------------------------------------
// kz: trivial init (exists so the profiled launch #4 is k2b)
// ---------------------------------------------------------------------------
__global__ void kz_init() {
    if (threadIdx.x == 0) g_red[0][0][0] = 0.f;
}

// ---------------------------------------------------------------------------
// Kernel 1: h = gelu(z @ W0 + b0) -> g_h fp32 [b][k].  (proven FFMA version)
// ---------------------------------------------------------------------------
__global__ void __launch_bounds__(256) k1_gemm0(const float* __restrict__ z,
                                                const float* __restrict__ W0,
                                                const float* __restrict__ b0) {
    __shared__ float zs[4][DMEAN];
    const int tid = threadIdx.x;
    const int col = blockIdx.x * 64 + (tid & 63);
    const int bg  = blockIdx.y;
    const int brow = bg * 4 + (tid >> 6);

    for (int i = tid; i < 4 * DMEAN; i += 256) {
        int bb = i >> 10, kk = i & 1023;
        zs[bb][kk] = z[(bg * 4 + bb) * DMEAN + kk];
    }
    __syncthreads();

    const float* zr = zs[tid >> 6];
    const float* wp = W0 + col;
    float acc = 0.f;
#pragma unroll 32
    for (int k = 0; k < DMEAN; k++) {
        acc = fmaf(zr[k], wp[(size_t)k * DMV], acc);
    }
    float x = acc + b0[col];
    g_h[brow * DMV + col] = 0.5f * x * (1.f + erff(x * 0.70710678118654752f));
}

// ---------------------------------------------------------------------------
// Kernel 2: logits tile = h @ W1 + b1.  TF32 mma, 256 thr, DEPTH-4 pipeline.
// A tile fills with 16B cp.async: row k starts (k&3) words past a 16B
// boundary (VOCAB % 4 == 1, vb % 4 == 0), so copy 34 aligned granules from
// align_down(start) into the 136-word padded row; fragment loads add (lane&3).
// Clamp min(gs, TOTW-4): only the final W1 row of the last block overruns, and
// its spilled words map exclusively to columns >= VOCAB (unused).
// ---------------------------------------------------------------------------
__global__ void __launch_bounds__(256) k2_mma(const float* __restrict__ W1,
                                              const float* __restrict__ b1,
                                              int vb0) {
    extern __shared__ char sm[];
    const uint32_t smb = (uint32_t)__cvta_generic_to_shared(sm);
    const uint32_t bsb = smb + DEPTH * AW_STG * 4;
    const int t = threadIdx.x, w = t >> 5, lane = t & 31;
    const int vb = vb0 + blockIdx.x * TM;

    auto fill = [&](int s) {
        const int buf = s & (DEPTH - 1);
        const uint32_t Ab = smb + buf * AW_STG * 4;
        const uint32_t Bb = bsb + buf * BW_STG * 4;
        const int kr = s * KSTG;
        // A: 32 rows x 34 granules = 1088 16B copies
#pragma unroll
        for (int i = 0; i < 5; i++) {
            int idx = t + i * 256;
            if (idx < 1088) {
                int k = idx / 34, g = idx % 34;
                size_t g0 = (size_t)(kr + k) * VOCAB + vb;
                size_t gs = g0 - (size_t)(k & 3) + 4 * (size_t)g;
                if (gs > TOTW - 4) gs = TOTW - 4;
                cp_async16(Ab + (uint32_t)(k * AST + 4 * g) * 4, W1 + gs);
            }
        }
        // B: 256 16B copies (1/thread) from g_h (16B-aligned rows)
        {
            int n = t >> 3, g = t & 7;
            cp_async16(Bb + (uint32_t)(n * BST + 4 * g) * 4,
                       g_h + (size_t)n * DMV + kr + 4 * g);
        }
    };

    fill(0); CP_COMMIT();
    fill(1); CP_COMMIT();
    fill(2); CP_COMMIT();

    float acc[4][4];
#pragma unroll
    for (int j = 0; j < 4; j++)
#pragma unroll
        for (int q = 0; q < 4; q++) acc[j][q] = 0.f;

    const int la = lane & 3;
    const int mfrag = w * 16 + (lane >> 2);

    for (int s = 0; s < NSTG; s++) {
        CP_WAIT2();
        __syncthreads();
        if (s + 3 < NSTG) fill(s + 3);
        CP_COMMIT();

        const int buf = s & (DEPTH - 1);
        const uint32_t Ab = smb + buf * AW_STG * 4;
        const uint32_t Bb = bsb + buf * BW_STG * 4;
#pragma unroll
        for (int ks = 0; ks < 4; ks++) {
            const int kb = ks * 8;
            uint32_t a[4], bf[4][2];
            {
                // A[m][k] at smem word (k*AST + (k&3) + m); (kb+la)&3 == la
                uint32_t r0 = Ab + (uint32_t)((kb + la) * AST + mfrag + la) * 4;
                a[0] = lds32(r0);
                a[1] = lds32(r0 + 8 * 4);
                a[2] = lds32(r0 + 4 * AST * 4);
                a[3] = lds32(r0 + (4 * AST + 8) * 4);
            }
#pragma unroll
            for (int ns = 0; ns < 4; ns++) {
                int n = ns * 8 + (lane >> 2);
                uint32_t r0 = Bb + (uint32_t)(n * BST + kb + la) * 4;
                bf[ns][0] = lds32(r0);
                bf[ns][1] = lds32(r0 + 4 * 4);
            }
#pragma unroll
            for (int ns = 0; ns < 4; ns++)
                MMA1688(acc[ns], a, bf[ns][0], bf[ns][1]);
        }
    }

    // epilogue
    {
        int v0 = vb + w * 16 + (lane >> 2);
        int v1 = v0 + 8;
        float bi0 = b1[min(v0, VOCAB - 1)];
        float bi1 = b1[min(v1, VOCAB - 1)];
#pragma unroll
        for (int ns = 0; ns < 4; ns++) {
            int b = ns * 8 + (lane & 3) * 2;
            if (v0 < VOCAB) {
                g_logits[(size_t)b * VOCAB + v0]       = acc[ns][0] + bi0;
                g_logits[(size_t)(b + 1) * VOCAB + v0] = acc[ns][1] + bi0;
            }
            if (v1 < VOCAB) {
                g_logits[(size_t)b * VOCAB + v1]       = acc[ns][2] + bi1;
                g_logits[(size_t)(b + 1) * VOCAB + v1] = acc[ns][3] + bi1;
            }
        }
    }
}

// ---------------------------------------------------------------------------
// Kernel 3a: per (row, slice) max + sumexp.  grid (NSL, BATCH) = 256 blocks.
// ---------------------------------------------------------------------------
__global__ void __launch_bounds__(256) k3a_slice() {
    const int b = blockIdx.y, sl = blockIdx.x;
    const int tid = threadIdx.x;
    const int v0 = sl * SLW, v1 = min(v0 + SLW, VOCAB);
    const float* row = g_logits + (size_t)b * VOCAB;
    __shared__ float red[256];

    float m = -INFINITY;
    for (int v = v0 + tid; v < v1; v += 256) m = fmaxf(m, row[v]);
    red[tid] = m; __syncthreads();
    for (int s = 128; s > 0; s >>= 1) {
        if (tid < s) red[tid] = fmaxf(red[tid], red[tid + s]);
        __syncthreads();
    }
    const float M = red[0]; __syncthreads();

    float ssum = 0.f;
    for (int v = v0 + tid; v < v1; v += 256) ssum += expf(row[v] - M);
    red[tid] = ssum; __syncthreads();
    for (int s = 128; s > 0; s >>= 1) {
        if (tid < s) red[tid] += red[tid + s];
        __syncthreads();
    }
    if (tid == 0) { g_red[b][sl][0] = M; g_red[b][sl][1] = red[0]; }
}

// ---------------------------------------------------------------------------
// Kernel 3b: combine slices + label gather + final mean.  1 block, 512 thr.
// Deterministic: fixed thread->(b,s) mapping, tree reductions, serial finals.
// ---------------------------------------------------------------------------
__global__ void __launch_bounds__(512) k3b_final(const int* __restrict__ labels,
                                                 float* __restrict__ out) {
    __shared__ float gsum[BATCH][16];
    __shared__ float rowpart[BATCH];
    const int tid = threadIdx.x;
    const int b = tid >> 4, sl16 = tid & 15;   // 32 x 16 = 512

    // gather: thread (b, sl16) sums labels s = sl16, sl16+16, ... (8 each)
    float gacc = 0.f;
    const float* row = g_logits + (size_t)b * VOCAB;
#pragma unroll
    for (int i = 0; i < 8; i++) {
        int s = sl16 + 16 * i;
        int lv = labels[b * SEQL + s];
        lv = max(0, min(lv, VOCAB - 1));
        gacc += row[lv];
    }
    gsum[b][sl16] = gacc;
    __syncthreads();
    for (int s = 8; s > 0; s >>= 1) {
        if (sl16 < s) gsum[b][sl16] += gsum[b][sl16 + s];
        __syncthreads();
    }

    // per-row LSE from slice partials (serial over 8 slices, deterministic)
    if (tid < BATCH) {
        float M = -INFINITY;
#pragma unroll
        for (int i = 0; i < NSL; i++) M = fmaxf(M, g_red[tid][i][0]);
        float S = 0.f;
#pragma unroll
        for (int i = 0; i < NSL; i++)
            S += g_red[tid][i][1] * expf(g_red[tid][i][0] - M);
        rowpart[tid] = (float)SEQL * (M + logf(S)) - gsum[tid][0];
    }
    __syncthreads();
    if (tid == 0) {
        float s = 0.f;
        for (int i = 0; i < BATCH; i++) s += rowpart[i];
        out[0] = s / (float)(BATCH * SEQL);
    }
}

// ---------------------------------------------------------------------------
extern "C" void kernel_launch(void* const* d_in, const int* in_sizes, int n_in,
                              void* d_out, int out_size) {
    const float* z      = (const float*)d_in[0];
    const int*   labels = (const int*)d_in[1];
    const float* W0     = (const float*)d_in[2];
    const float* b0     = (const float*)d_in[3];
    const float* W1     = (const float*)d_in[4];
    const float* b1     = (const float*)d_in[5];
    float* out = (float*)d_out;

    cudaFuncSetAttribute(k2_mma, cudaFuncAttributeMaxDynamicSharedMemorySize,
                         K2_SMEM);

    kz_init<<<1, 32>>>();                               // launch 1
    k1_gemm0<<<dim3(16, 8), 256>>>(z, W0, b0);          // launch 2
    k2_mma<<<NB2A, 256, K2_SMEM>>>(W1, b1, 0);          // launch 3
    k2_mma<<<NB2B, 256, K2_SMEM>>>(W1, b1, VB_B);       // launch 4 <- profiled
    k3a_slice<<<dim3(NSL, BATCH), 256>>>();             // launch 5
    k3b_final<<<1, 512>>>(labels, out);                 // launch 6
}

// round 11
// speedup vs baseline: 1.3881x; 1.1784x over previous
#include <cuda_runtime.h>
#include <cuda_bf16.h>
#include <math.h>
#include <stdint.h>

#define VOCAB 50257
#define DMEAN 1024
#define DMV   1024
#define BATCH 32
#define SEQL  128
#define TOTW  ((size_t)DMV * VOCAB)       // W1 total words

// ---- k2 tf32 pipeline config (256 threads / 8 warps per block) ----
#define TM      128
#define KSTG    32
#define NSTG    (DMV / KSTG)              // 32
#define DEPTH   3                         // 67.6KB smem -> 2-3 blocks/SM
#define AST     136                       // 34 x 16B granules per k-row (pad incl)
#define BST     40
#define AW_STG  (KSTG * AST)              // 4352 words
#define BW_STG  (BATCH * BST)             // 1280 words
#define K2_SMEM ((DEPTH * (AW_STG + BW_STG)) * 4)   // 67584 B
#define NBV     ((VOCAB + TM - 1) / TM)   // 393 (single merged launch)

// ---- k3 split ----
#define NSL     8
#define SLW     6283                      // ceil(VOCAB/8)

// Scratch (device globals — no runtime allocation allowed)
__device__ float g_h[BATCH * DMV];
__device__ float g_logits[BATCH * VOCAB];
__device__ float g_red[BATCH][NSL][2];    // per-slice {max, sumexp}

// ---------------------------------------------------------------------------
#define MMA1688(c, a, bb0, bb1)                                                \
    asm volatile("mma.sync.aligned.m16n8k8.row.col.f32.tf32.tf32.f32 "         \
                 "{%0,%1,%2,%3}, {%4,%5,%6,%7}, {%8,%9}, {%0,%1,%2,%3};"       \
                 : "+f"(c[0]), "+f"(c[1]), "+f"(c[2]), "+f"(c[3])              \
                 : "r"(a[0]), "r"(a[1]), "r"(a[2]), "r"(a[3]),                 \
                   "r"(bb0), "r"(bb1))

__device__ __forceinline__ void cp_async16(uint32_t dst, const void* src) {
    asm volatile("cp.async.cg.shared.global [%0], [%1], 16;"
                 :: "r"(dst), "l"(src) : "memory");
}
__device__ __forceinline__ uint32_t lds32(uint32_t a) {
    uint32_t v;
    asm volatile("ld.shared.b32 %0, [%1];" : "=r"(v) : "r"(a));
    return v;
}
#define CP_COMMIT() asm volatile("cp.async.commit_group;" ::: "memory")
#define CP_WAIT1()  asm volatile("cp.async.wait_group 1;" ::: "memory")

// ---------------------------------------------------------------------------
// kz: trivial init (x2 so the profiled launch #4 is the merged k2)
// ---------------------------------------------------------------------------
__global__ void kz_init() {
    if (threadIdx.x == 0) g_red[0][0][0] = 0.f;
}

// ---------------------------------------------------------------------------
// Kernel 1: h = gelu(z @ W0 + b0) -> g_h fp32 [b][k].  (proven FFMA version)
// ---------------------------------------------------------------------------
__global__ void __launch_bounds__(256) k1_gemm0(const float* __restrict__ z,
                                                const float* __restrict__ W0,
                                                const float* __restrict__ b0) {
    __shared__ float zs[4][DMEAN];
    const int tid = threadIdx.x;
    const int col = blockIdx.x * 64 + (tid & 63);
    const int bg  = blockIdx.y;
    const int brow = bg * 4 + (tid >> 6);

    for (int i = tid; i < 4 * DMEAN; i += 256) {
        int bb = i >> 10, kk = i & 1023;
        zs[bb][kk] = z[(bg * 4 + bb) * DMEAN + kk];
    }
    __syncthreads();

    const float* zr = zs[tid >> 6];
    const float* wp = W0 + col;
    float acc = 0.f;
#pragma unroll 32
    for (int k = 0; k < DMEAN; k++) {
        acc = fmaf(zr[k], wp[(size_t)k * DMV], acc);
    }
    float x = acc + b0[col];
    g_h[brow * DMV + col] = 0.5f * x * (1.f + erff(x * 0.70710678118654752f));
}

// ---------------------------------------------------------------------------
// Kernel 2: logits = h @ W1 + b1.  TF32 mma, 256 thr, DEPTH-3 pipeline,
// single merged launch (393 blocks). A tile via 16B cp.async from the
// aligned-down W1 row start (VOCAB odd: row k is (k&3) words past 16B);
// fragment loads add (lane&3). Tail clamp min(gs, TOTW-4) is safe: spill
// words map only to columns >= VOCAB.
// ---------------------------------------------------------------------------
__global__ void __launch_bounds__(256) k2_mma(const float* __restrict__ W1,
                                              const float* __restrict__ b1) {
    extern __shared__ char sm[];
    const uint32_t smb = (uint32_t)__cvta_generic_to_shared(sm);
    const uint32_t bsb = smb + DEPTH * AW_STG * 4;
    const int t = threadIdx.x, w = t >> 5, lane = t & 31;
    const int vb = blockIdx.x * TM;

    auto fill = [&](int s) {
        const int buf = s % DEPTH;
        const uint32_t Ab = smb + buf * AW_STG * 4;
        const uint32_t Bb = bsb + buf * BW_STG * 4;
        const int kr = s * KSTG;
        // A: 32 rows x 34 granules = 1088 16B copies
#pragma unroll
        for (int i = 0; i < 5; i++) {
            int idx = t + i * 256;
            if (idx < 1088) {
                int k = idx / 34, g = idx % 34;
                size_t g0 = (size_t)(kr + k) * VOCAB + vb;
                size_t gs = g0 - (size_t)(k & 3) + 4 * (size_t)g;
                if (gs > TOTW - 4) gs = TOTW - 4;
                cp_async16(Ab + (uint32_t)(k * AST + 4 * g) * 4, W1 + gs);
            }
        }
        // B: 256 16B copies (1/thread) from g_h (16B-aligned rows)
        {
            int n = t >> 3, g = t & 7;
            cp_async16(Bb + (uint32_t)(n * BST + 4 * g) * 4,
                       g_h + (size_t)n * DMV + kr + 4 * g);
        }
    };

    fill(0); CP_COMMIT();
    fill(1); CP_COMMIT();

    float acc[4][4];
#pragma unroll
    for (int j = 0; j < 4; j++)
#pragma unroll
        for (int q = 0; q < 4; q++) acc[j][q] = 0.f;

    const int la = lane & 3;
    const int mfrag = w * 16 + (lane >> 2);

    for (int s = 0; s < NSTG; s++) {
        CP_WAIT1();
        __syncthreads();                  // stage s arrived; buf (s-1)%3 free
        if (s + 2 < NSTG) fill(s + 2);
        CP_COMMIT();                      // commit every iter (group accounting)

        const int buf = s % DEPTH;
        const uint32_t Ab = smb + buf * AW_STG * 4;
        const uint32_t Bb = bsb + buf * BW_STG * 4;
#pragma unroll
        for (int ks = 0; ks < 4; ks++) {
            const int kb = ks * 8;
            uint32_t a[4], bf[4][2];
            {
                // A[m][k] at smem word (k*AST + (k&3) + m); (kb+la)&3 == la
                uint32_t r0 = Ab + (uint32_t)((kb + la) * AST + mfrag + la) * 4;
                a[0] = lds32(r0);
                a[1] = lds32(r0 + 8 * 4);
                a[2] = lds32(r0 + 4 * AST * 4);
                a[3] = lds32(r0 + (4 * AST + 8) * 4);
            }
#pragma unroll
            for (int ns = 0; ns < 4; ns++) {
                int n = ns * 8 + (lane >> 2);
                uint32_t r0 = Bb + (uint32_t)(n * BST + kb + la) * 4;
                bf[ns][0] = lds32(r0);
                bf[ns][1] = lds32(r0 + 4 * 4);
            }
#pragma unroll
            for (int ns = 0; ns < 4; ns++)
                MMA1688(acc[ns], a, bf[ns][0], bf[ns][1]);
        }
    }

    // epilogue
    {
        int v0 = vb + w * 16 + (lane >> 2);
        int v1 = v0 + 8;
        float bi0 = b1[min(v0, VOCAB - 1)];
        float bi1 = b1[min(v1, VOCAB - 1)];
#pragma unroll
        for (int ns = 0; ns < 4; ns++) {
            int b = ns * 8 + (lane & 3) * 2;
            if (v0 < VOCAB) {
                g_logits[(size_t)b * VOCAB + v0]       = acc[ns][0] + bi0;
                g_logits[(size_t)(b + 1) * VOCAB + v0] = acc[ns][1] + bi0;
            }
            if (v1 < VOCAB) {
                g_logits[(size_t)b * VOCAB + v1]       = acc[ns][2] + bi1;
                g_logits[(size_t)(b + 1) * VOCAB + v1] = acc[ns][3] + bi1;
            }
        }
    }
}

// ---------------------------------------------------------------------------
// Kernel 3a: per (row, slice) max + sumexp.  grid (NSL, BATCH) = 256 blocks.
// ---------------------------------------------------------------------------
__global__ void __launch_bounds__(256) k3a_slice() {
    const int b = blockIdx.y, sl = blockIdx.x;
    const int tid = threadIdx.x;
    const int v0 = sl * SLW, v1 = min(v0 + SLW, VOCAB);
    const float* row = g_logits + (size_t)b * VOCAB;
    __shared__ float red[256];

    float m = -INFINITY;
    for (int v = v0 + tid; v < v1; v += 256) m = fmaxf(m, row[v]);
    red[tid] = m; __syncthreads();
    for (int s = 128; s > 0; s >>= 1) {
        if (tid < s) red[tid] = fmaxf(red[tid], red[tid + s]);
        __syncthreads();
    }
    const float M = red[0]; __syncthreads();

    float ssum = 0.f;
    for (int v = v0 + tid; v < v1; v += 256) ssum += expf(row[v] - M);
    red[tid] = ssum; __syncthreads();
    for (int s = 128; s > 0; s >>= 1) {
        if (tid < s) red[tid] += red[tid + s];
        __syncthreads();
    }
    if (tid == 0) { g_red[b][sl][0] = M; g_red[b][sl][1] = red[0]; }
}

// ---------------------------------------------------------------------------
// Kernel 3b: combine slices + label gather + final mean.  1 block, 512 thr.
// ---------------------------------------------------------------------------
__global__ void __launch_bounds__(512) k3b_final(const int* __restrict__ labels,
                                                 float* __restrict__ out) {
    __shared__ float gsum[BATCH][16];
    __shared__ float rowpart[BATCH];
    const int tid = threadIdx.x;
    const int b = tid >> 4, sl16 = tid & 15;   // 32 x 16 = 512

    float gacc = 0.f;
    const float* row = g_logits + (size_t)b * VOCAB;
#pragma unroll
    for (int i = 0; i < 8; i++) {
        int s = sl16 + 16 * i;
        int lv = labels[b * SEQL + s];
        lv = max(0, min(lv, VOCAB - 1));
        gacc += row[lv];
    }
    gsum[b][sl16] = gacc;
    __syncthreads();
    for (int s = 8; s > 0; s >>= 1) {
        if (sl16 < s) gsum[b][sl16] += gsum[b][sl16 + s];
        __syncthreads();
    }

    if (tid < BATCH) {
        float M = -INFINITY;
#pragma unroll
        for (int i = 0; i < NSL; i++) M = fmaxf(M, g_red[tid][i][0]);
        float S = 0.f;
#pragma unroll
        for (int i = 0; i < NSL; i++)
            S += g_red[tid][i][1] * expf(g_red[tid][i][0] - M);
        rowpart[tid] = (float)SEQL * (M + logf(S)) - gsum[tid][0];
    }
    __syncthreads();
    if (tid == 0) {
        float s = 0.f;
        for (int i = 0; i < BATCH; i++) s += rowpart[i];
        out[0] = s / (float)(BATCH * SEQL);
    }
}

// ---------------------------------------------------------------------------
extern "C" void kernel_launch(void* const* d_in, const int* in_sizes, int n_in,
                              void* d_out, int out_size) {
    const float* z      = (const float*)d_in[0];
    const int*   labels = (const int*)d_in[1];
    const float* W0     = (const float*)d_in[2];
    const float* b0     = (const float*)d_in[3];
    const float* W1     = (const float*)d_in[4];
    const float* b1     = (const float*)d_in[5];
    float* out = (float*)d_out;

    cudaFuncSetAttribute(k2_mma, cudaFuncAttributeMaxDynamicSharedMemorySize,
                         K2_SMEM);

    kz_init<<<1, 32>>>();                               // launch 1
    kz_init<<<1, 32>>>();                               // launch 2
    k1_gemm0<<<dim3(16, 8), 256>>>(z, W0, b0);          // launch 3
    k2_mma<<<NBV, 256, K2_SMEM>>>(W1, b1);              // launch 4 <- profiled
    k3a_slice<<<dim3(NSL, BATCH), 256>>>();             // launch 5
    k3b_final<<<1, 512>>>(labels, out);                 // launch 6
}

// round 12
// speedup vs baseline: 1.5051x; 1.0843x over previous
#include <cuda_runtime.h>
#include <cuda_bf16.h>
#include <math.h>
#include <stdint.h>

#define VOCAB 50257
#define DMEAN 1024
#define DMV   1024
#define BATCH 32
#define SEQL  128
#define TOTW  ((size_t)DMV * VOCAB)       // W1 total words

// ---- k2 tf32 pipeline config (256 threads / 8 warps per block) ----
#define TM      128
#define KSTG    32
#define NSTG    (DMV / KSTG)              // 32
#define DEPTH   3
#define AST     136                       // A k-row stride (34 granules); frag 2-way on 3/32 banks only
#define BST     36                        // B n-row stride: 36 % 32 == 4 -> conflict-free frags
#define AW_STG  (KSTG * AST)              // 4352 words
#define BW_STG  (BATCH * BST)             // 1152 words
#define K2_SMEM ((DEPTH * (AW_STG + BW_STG)) * 4)   // 66048 B -> 3 blocks/SM
#define NBV     ((VOCAB + TM - 1) / TM)   // 393

// ---- k3 split ----
#define NSL     8
#define SLW     6283                      // ceil(VOCAB/8)

// Scratch (device globals — no runtime allocation allowed)
__device__ float g_h[BATCH * DMV];
__device__ float g_logits[BATCH * VOCAB];
__device__ float g_red[BATCH][NSL][2];    // per-slice {max, sumexp}

// ---------------------------------------------------------------------------
#define MMA1688(c, a, bb0, bb1)                                                \
    asm volatile("mma.sync.aligned.m16n8k8.row.col.f32.tf32.tf32.f32 "         \
                 "{%0,%1,%2,%3}, {%4,%5,%6,%7}, {%8,%9}, {%0,%1,%2,%3};"       \
                 : "+f"(c[0]), "+f"(c[1]), "+f"(c[2]), "+f"(c[3])              \
                 : "r"(a[0]), "r"(a[1]), "r"(a[2]), "r"(a[3]),                 \
                   "r"(bb0), "r"(bb1))

__device__ __forceinline__ void cp_async16(uint32_t dst, const void* src) {
    asm volatile("cp.async.cg.shared.global [%0], [%1], 16;"
                 :: "r"(dst), "l"(src) : "memory");
}
__device__ __forceinline__ uint32_t lds32(uint32_t a) {
    uint32_t v;
    asm volatile("ld.shared.b32 %0, [%1];" : "=r"(v) : "r"(a));
    return v;
}
#define CP_COMMIT() asm volatile("cp.async.commit_group;" ::: "memory")
#define CP_WAIT1()  asm volatile("cp.async.wait_group 1;" ::: "memory")

// ---------------------------------------------------------------------------
// kz: trivial init (x2 so the profiled launch #4 is k2)
// ---------------------------------------------------------------------------
__global__ void kz_init() {
    if (threadIdx.x == 0) g_red[0][0][0] = 0.f;
}

// ---------------------------------------------------------------------------
// Kernel 1: h = gelu(z @ W0 + b0) -> g_h fp32 [b][k].  (proven FFMA version)
// ---------------------------------------------------------------------------
__global__ void __launch_bounds__(256) k1_gemm0(const float* __restrict__ z,
                                                const float* __restrict__ W0,
                                                const float* __restrict__ b0) {
    __shared__ float zs[4][DMEAN];
    const int tid = threadIdx.x;
    const int col = blockIdx.x * 64 + (tid & 63);
    const int bg  = blockIdx.y;
    const int brow = bg * 4 + (tid >> 6);

    for (int i = tid; i < 4 * DMEAN; i += 256) {
        int bb = i >> 10, kk = i & 1023;
        zs[bb][kk] = z[(bg * 4 + bb) * DMEAN + kk];
    }
    __syncthreads();

    const float* zr = zs[tid >> 6];
    const float* wp = W0 + col;
    float acc = 0.f;
#pragma unroll 32
    for (int k = 0; k < DMEAN; k++) {
        acc = fmaf(zr[k], wp[(size_t)k * DMV], acc);
    }
    float x = acc + b0[col];
    g_h[brow * DMV + col] = 0.5f * x * (1.f + erff(x * 0.70710678118654752f));
}

// ---------------------------------------------------------------------------
// Kernel 2: logits = h @ W1 + b1.  TF32 mma, 256 thr, DEPTH-3 pipeline,
// 393 blocks, target 3 blocks/SM. A tile via 16B cp.async from aligned-down
// W1 row starts (VOCAB odd); fragment loads add (lane&3). B frags now
// conflict-free (BST=36).
// ---------------------------------------------------------------------------
__global__ void __launch_bounds__(256, 3) k2_mma(const float* __restrict__ W1,
                                                 const float* __restrict__ b1) {
    extern __shared__ char sm[];
    const uint32_t smb = (uint32_t)__cvta_generic_to_shared(sm);
    const uint32_t bsb = smb + DEPTH * AW_STG * 4;
    const int t = threadIdx.x, w = t >> 5, lane = t & 31;
    const int vb = blockIdx.x * TM;

    auto fill = [&](int s, int buf) {
        const uint32_t Ab = smb + buf * AW_STG * 4;
        const uint32_t Bb = bsb + buf * BW_STG * 4;
        const int kr = s * KSTG;
        // A: 32 rows x 34 granules = 1088 16B copies
#pragma unroll
        for (int i = 0; i < 5; i++) {
            int idx = t + i * 256;
            if (idx < 1088) {
                int k = idx / 34, g = idx % 34;
                size_t g0 = (size_t)(kr + k) * VOCAB + vb;
                size_t gs = g0 - (size_t)(k & 3) + 4 * (size_t)g;
                if (gs > TOTW - 4) gs = TOTW - 4;
                cp_async16(Ab + (uint32_t)(k * AST + 4 * g) * 4, W1 + gs);
            }
        }
        // B: 256 16B copies (1/thread) from g_h (16B-aligned rows)
        {
            int n = t >> 3, g = t & 7;
            cp_async16(Bb + (uint32_t)(n * BST + 4 * g) * 4,
                       g_h + (size_t)n * DMV + kr + 4 * g);
        }
    };

    fill(0, 0); CP_COMMIT();
    fill(1, 1); CP_COMMIT();

    float acc[4][4];
#pragma unroll
    for (int j = 0; j < 4; j++)
#pragma unroll
        for (int q = 0; q < 4; q++) acc[j][q] = 0.f;

    const int la = lane & 3;
    const int mfrag = w * 16 + (lane >> 2);

    int buf = 0, pf = 2;                  // consume buf, prefetch into pf
    for (int s = 0; s < NSTG; s++) {
        CP_WAIT1();
        __syncthreads();                  // stage s arrived; buf (s-1)%3 free
        if (s + 2 < NSTG) fill(s + 2, pf);
        CP_COMMIT();                      // commit every iter (group accounting)

        const uint32_t Ab = smb + buf * AW_STG * 4;
        const uint32_t Bb = bsb + buf * BW_STG * 4;
#pragma unroll
        for (int ks = 0; ks < 4; ks++) {
            const int kb = ks * 8;
            uint32_t a[4], bf[4][2];
            {
                // A[m][k] at smem word (k*AST + (k&3) + m); (kb+la)&3 == la
                uint32_t r0 = Ab + (uint32_t)((kb + la) * AST + mfrag + la) * 4;
                a[0] = lds32(r0);
                a[1] = lds32(r0 + 8 * 4);
                a[2] = lds32(r0 + 4 * AST * 4);
                a[3] = lds32(r0 + (4 * AST + 8) * 4);
            }
#pragma unroll
            for (int ns = 0; ns < 4; ns++) {
                int n = ns * 8 + (lane >> 2);
                uint32_t r0 = Bb + (uint32_t)(n * BST + kb + la) * 4;
                bf[ns][0] = lds32(r0);
                bf[ns][1] = lds32(r0 + 4 * 4);
            }
#pragma unroll
            for (int ns = 0; ns < 4; ns++)
                MMA1688(acc[ns], a, bf[ns][0], bf[ns][1]);
        }
        buf = (buf == DEPTH - 1) ? 0 : buf + 1;
        pf  = (pf  == DEPTH - 1) ? 0 : pf + 1;
    }

    // epilogue
    {
        int v0 = vb + w * 16 + (lane >> 2);
        int v1 = v0 + 8;
        float bi0 = b1[min(v0, VOCAB - 1)];
        float bi1 = b1[min(v1, VOCAB - 1)];
#pragma unroll
        for (int ns = 0; ns < 4; ns++) {
            int b = ns * 8 + (lane & 3) * 2;
            if (v0 < VOCAB) {
                g_logits[(size_t)b * VOCAB + v0]       = acc[ns][0] + bi0;
                g_logits[(size_t)(b + 1) * VOCAB + v0] = acc[ns][1] + bi0;
            }
            if (v1 < VOCAB) {
                g_logits[(size_t)b * VOCAB + v1]       = acc[ns][2] + bi1;
                g_logits[(size_t)(b + 1) * VOCAB + v1] = acc[ns][3] + bi1;
            }
        }
    }
}

// ---------------------------------------------------------------------------
// Kernel 3a: per (row, slice) max + sumexp.  grid (NSL, BATCH) = 256 blocks.
// ---------------------------------------------------------------------------
__global__ void __launch_bounds__(256) k3a_slice() {
    const int b = blockIdx.y, sl = blockIdx.x;
    const int tid = threadIdx.x;
    const int v0 = sl * SLW, v1 = min(v0 + SLW, VOCAB);
    const float* row = g_logits + (size_t)b * VOCAB;
    __shared__ float red[256];

    float m = -INFINITY;
    for (int v = v0 + tid; v < v1; v += 256) m = fmaxf(m, row[v]);
    red[tid] = m; __syncthreads();
    for (int s = 128; s > 0; s >>= 1) {
        if (tid < s) red[tid] = fmaxf(red[tid], red[tid + s]);
        __syncthreads();
    }
    const float M = red[0]; __syncthreads();

    float ssum = 0.f;
    for (int v = v0 + tid; v < v1; v += 256) ssum += expf(row[v] - M);
    red[tid] = ssum; __syncthreads();
    for (int s = 128; s > 0; s >>= 1) {
        if (tid < s) red[tid] += red[tid + s];
        __syncthreads();
    }
    if (tid == 0) { g_red[b][sl][0] = M; g_red[b][sl][1] = red[0]; }
}

// ---------------------------------------------------------------------------
// Kernel 3b: combine slices + label gather + final mean.  1 block, 512 thr.
// ---------------------------------------------------------------------------
__global__ void __launch_bounds__(512) k3b_final(const int* __restrict__ labels,
                                                 float* __restrict__ out) {
    __shared__ float gsum[BATCH][16];
    __shared__ float rowpart[BATCH];
    const int tid = threadIdx.x;
    const int b = tid >> 4, sl16 = tid & 15;   // 32 x 16 = 512

    float gacc = 0.f;
    const float* row = g_logits + (size_t)b * VOCAB;
#pragma unroll
    for (int i = 0; i < 8; i++) {
        int s = sl16 + 16 * i;
        int lv = labels[b * SEQL + s];
        lv = max(0, min(lv, VOCAB - 1));
        gacc += row[lv];
    }
    gsum[b][sl16] = gacc;
    __syncthreads();
    for (int s = 8; s > 0; s >>= 1) {
        if (sl16 < s) gsum[b][sl16] += gsum[b][sl16 + s];
        __syncthreads();
    }

    if (tid < BATCH) {
        float M = -INFINITY;
#pragma unroll
        for (int i = 0; i < NSL; i++) M = fmaxf(M, g_red[tid][i][0]);
        float S = 0.f;
#pragma unroll
        for (int i = 0; i < NSL; i++)
            S += g_red[tid][i][1] * expf(g_red[tid][i][0] - M);
        rowpart[tid] = (float)SEQL * (M + logf(S)) - gsum[tid][0];
    }
    __syncthreads();
    if (tid == 0) {
        float s = 0.f;
        for (int i = 0; i < BATCH; i++) s += rowpart[i];
        out[0] = s / (float)(BATCH * SEQL);
    }
}

// ---------------------------------------------------------------------------
extern "C" void kernel_launch(void* const* d_in, const int* in_sizes, int n_in,
                              void* d_out, int out_size) {
    const float* z      = (const float*)d_in[0];
    const int*   labels = (const int*)d_in[1];
    const float* W0     = (const float*)d_in[2];
    const float* b0     = (const float*)d_in[3];
    const float* W1     = (const float*)d_in[4];
    const float* b1     = (const float*)d_in[5];
    float* out = (float*)d_out;

    cudaFuncSetAttribute(k2_mma, cudaFuncAttributeMaxDynamicSharedMemorySize,
                         K2_SMEM);

    kz_init<<<1, 32>>>();                               // launch 1
    kz_init<<<1, 32>>>();                               // launch 2
    k1_gemm0<<<dim3(16, 8), 256>>>(z, W0, b0);          // launch 3
    k2_mma<<<NBV, 256, K2_SMEM>>>(W1, b1);              // launch 4 <- profiled
    k3a_slice<<<dim3(NSL, BATCH), 256>>>();             // launch 5
    k3b_final<<<1, 512>>>(labels, out);                 // launch 6
}